// round 4
// baseline (speedup 1.0000x reference)
#include <cuda_runtime.h>
#include <math.h>

#define N_ATOMS 40000
#define N_BONDS 90000
#define MAX_NB 6
#define ATOM_FDIM 133
#define BOND_FDIM 147
#define HID 300
#define DEPTH 6
#define CAT_DIM (ATOM_FDIM + HID)   // 433

#define H4   (HID / 4)              // 75
#define H34  (3 * HID / 4)          // 225

// ---------------- scratch (device globals; no cudaMalloc allowed) -------------
__device__ float g_inp [N_BONDS * HID];
__device__ float g_gi  [N_BONDS * 3 * HID];
__device__ float g_msg [N_BONDS * HID];
__device__ float g_h   [N_BONDS * HID];
__device__ float g_gh  [N_BONDS * 3 * HID];
__device__ float g_amsg[N_ATOMS * HID];
__device__ float g_ain [N_ATOMS * CAT_DIM];

// ================= 3xTF32 tensor-core TN GEMM, presplit hi/lo in smem ==========
// C[m,n] = sum_k A[m,k] * B[n,k]  (+bias, relu, mask)
// x = hi + lo (hi = tf32(x), lo = tf32(x-hi)); C = hi*hi + hi*lo + lo*hi
// Smem stored in fragment-native layout:
//   A elem (row,k): lane=((row&7)<<2)|(k&3), reg=((row>>3)&1)|(((k>>2)&1)<<1)
//                   off = ((kb*8+mb)*32+lane)*4 + reg        (kb=k>>3, mb=row>>4)
//   B elem (n,k):   lane=((n&7)<<2)|(k&3),   reg=(k>>2)&1
//                   off = ((kb*16+nb)*32+lane)*2 + reg       (nb=n>>3)
#define BM 128
#define BN 128
#define BK 16

__device__ __forceinline__ void mma_tf32(float* c, const unsigned* a, const unsigned* b) {
    asm volatile(
        "mma.sync.aligned.m16n8k8.row.col.f32.tf32.tf32.f32 "
        "{%0,%1,%2,%3},{%4,%5,%6,%7},{%8,%9},{%0,%1,%2,%3};"
        : "+f"(c[0]), "+f"(c[1]), "+f"(c[2]), "+f"(c[3])
        : "r"(a[0]), "r"(a[1]), "r"(a[2]), "r"(a[3]), "r"(b[0]), "r"(b[1]));
}
__device__ __forceinline__ void tf32_split(float v, unsigned& hi, unsigned& lo) {
    asm("cvt.rna.tf32.f32 %0, %1;" : "=r"(hi) : "f"(v));
    float l = v - __uint_as_float(hi);
    asm("cvt.rna.tf32.f32 %0, %1;" : "=r"(lo) : "f"(l));
}

__global__ void __launch_bounds__(256)
mma_gemm_tn(const float* __restrict__ A, const float* __restrict__ B,
            const float* __restrict__ bias, const float* __restrict__ mask,
            float* __restrict__ C, int M, int N, int K, int relu)
{
    __shared__ alignas(16) float Ah[2][2048];
    __shared__ alignas(16) float Al[2][2048];
    __shared__ alignas(16) float Bh[2][2048];
    __shared__ alignas(16) float Bl[2][2048];

    const int tid  = threadIdx.x;
    const int wid  = tid >> 5;
    const int lane = tid & 31;
    const int warp_m = wid & 1;     // 2 warps along M (64 rows)
    const int warp_n = wid >> 1;    // 4 warps along N (32 cols)
    const int m0 = blockIdx.y * BM;
    const int n0 = blockIdx.x * BN;
    const int KT = (K + BK - 1) / BK;
    const bool vec = ((K & 3) == 0);

    float acc[4][4][4];
    #pragma unroll
    for (int mi = 0; mi < 4; mi++)
        #pragma unroll
        for (int ni = 0; ni < 4; ni++)
            #pragma unroll
            for (int r = 0; r < 4; r++) acc[mi][ni][r] = 0.f;

    float sa[8], sb[8];   // register staging for one tile

    auto ldg_tile = [&](int kt) {
        const int k0 = kt * BK;
        if (vec) {
            #pragma unroll
            for (int i = 0; i < 2; i++) {
                int idx = tid + i * 256;
                int row = idx >> 2, seg = idx & 3;
                int gk = k0 + seg * 4;
                int gm = m0 + row, gn = n0 + row;
                float4 va = (gm < M && gk < K) ? *(const float4*)(A + (size_t)gm * K + gk)
                                               : make_float4(0.f, 0.f, 0.f, 0.f);
                float4 vb = (gn < N && gk < K) ? *(const float4*)(B + (size_t)gn * K + gk)
                                               : make_float4(0.f, 0.f, 0.f, 0.f);
                sa[i*4+0]=va.x; sa[i*4+1]=va.y; sa[i*4+2]=va.z; sa[i*4+3]=va.w;
                sb[i*4+0]=vb.x; sb[i*4+1]=vb.y; sb[i*4+2]=vb.z; sb[i*4+3]=vb.w;
            }
        } else {
            #pragma unroll
            for (int i = 0; i < 8; i++) {
                int idx = tid + i * 256;
                int row = idx >> 4, kk = idx & 15;
                int gk = k0 + kk;
                int gm = m0 + row, gn = n0 + row;
                sa[i] = (gm < M && gk < K) ? A[(size_t)gm * K + gk] : 0.f;
                sb[i] = (gn < N && gk < K) ? B[(size_t)gn * K + gk] : 0.f;
            }
        }
    };

    auto sts_A = [&](int s, float v, int row, int k) {
        int kb = k >> 3, mb = row >> 4;
        int ln = ((row & 7) << 2) | (k & 3);
        int rg = ((row >> 3) & 1) | (((k >> 2) & 1) << 1);
        int off = ((kb * 8 + mb) * 32 + ln) * 4 + rg;
        unsigned hi, lo; tf32_split(v, hi, lo);
        Ah[s][off] = __uint_as_float(hi);
        Al[s][off] = __uint_as_float(lo);
    };
    auto sts_B = [&](int s, float v, int n, int k) {
        int kb = k >> 3, nb = n >> 3;
        int ln = ((n & 7) << 2) | (k & 3);
        int rg = (k >> 2) & 1;
        int off = ((kb * 16 + nb) * 32 + ln) * 2 + rg;
        unsigned hi, lo; tf32_split(v, hi, lo);
        Bh[s][off] = __uint_as_float(hi);
        Bl[s][off] = __uint_as_float(lo);
    };

    auto sts_tile = [&](int s) {
        if (vec) {
            #pragma unroll
            for (int i = 0; i < 2; i++) {
                int idx = tid + i * 256;
                int row = idx >> 2, seg = idx & 3;
                #pragma unroll
                for (int j = 0; j < 4; j++) {
                    sts_A(s, sa[i*4+j], row, seg * 4 + j);
                    sts_B(s, sb[i*4+j], row, seg * 4 + j);
                }
            }
        } else {
            #pragma unroll
            for (int i = 0; i < 8; i++) {
                int idx = tid + i * 256;
                int row = idx >> 4, kk = idx & 15;
                sts_A(s, sa[i], row, kk);
                sts_B(s, sb[i], row, kk);
            }
        }
    };

    ldg_tile(0);
    sts_tile(0);
    __syncthreads();

    for (int kt = 0; kt < KT; kt++) {
        const int cur = kt & 1;
        if (kt + 1 < KT) ldg_tile(kt + 1);

        #pragma unroll
        for (int kb = 0; kb < 2; kb++) {
            unsigned bhf[4][2], blf[4][2];
            #pragma unroll
            for (int ni = 0; ni < 4; ni++) {
                int nb = warp_n * 4 + ni;
                int boff = ((kb * 16 + nb) * 32 + lane) * 2;
                uint2 h2 = *(const uint2*)&Bh[cur][boff];
                uint2 l2 = *(const uint2*)&Bl[cur][boff];
                bhf[ni][0] = h2.x; bhf[ni][1] = h2.y;
                blf[ni][0] = l2.x; blf[ni][1] = l2.y;
            }
            #pragma unroll
            for (int mi = 0; mi < 4; mi++) {
                int mb = warp_m * 4 + mi;
                int aoff = ((kb * 8 + mb) * 32 + lane) * 4;
                uint4 ah4 = *(const uint4*)&Ah[cur][aoff];
                uint4 al4 = *(const uint4*)&Al[cur][aoff];
                unsigned ahf[4] = {ah4.x, ah4.y, ah4.z, ah4.w};
                unsigned alf[4] = {al4.x, al4.y, al4.z, al4.w};
                #pragma unroll
                for (int ni = 0; ni < 4; ni++) {
                    mma_tf32(acc[mi][ni], alf, bhf[ni]);   // lo*hi
                    mma_tf32(acc[mi][ni], ahf, blf[ni]);   // hi*lo
                    mma_tf32(acc[mi][ni], ahf, bhf[ni]);   // hi*hi
                }
            }
        }

        if (kt + 1 < KT) sts_tile((kt + 1) & 1);
        __syncthreads();
    }

    // epilogue
    const int g = lane >> 2, t = lane & 3;
    #pragma unroll
    for (int mi = 0; mi < 4; mi++) {
        #pragma unroll
        for (int ni = 0; ni < 4; ni++) {
            int cn = n0 + warp_n * 32 + ni * 8 + 2 * t;
            float b0 = 0.f, b1 = 0.f;
            if (bias) {
                if (cn     < N) b0 = bias[cn];
                if (cn + 1 < N) b1 = bias[cn + 1];
            }
            #pragma unroll
            for (int half = 0; half < 2; half++) {
                int rm = m0 + warp_m * 64 + mi * 16 + g + half * 8;
                if (rm >= M) continue;
                float v0 = acc[mi][ni][half * 2 + 0] + b0;
                float v1 = acc[mi][ni][half * 2 + 1] + b1;
                if (relu) { v0 = fmaxf(v0, 0.f); v1 = fmaxf(v1, 0.f); }
                if (mask) { float mk = mask[rm]; v0 *= mk; v1 *= mk; }
                if (cn + 1 < N) {
                    float2 v = {v0, v1};
                    *(float2*)(C + (size_t)rm * N + cn) = v;
                } else if (cn < N) {
                    C[(size_t)rm * N + cn] = v0;
                }
            }
        }
    }
}

// ================= elementwise (float4) =========================================
__global__ void gather_sum4(const float4* __restrict__ msg,
                            const int* __restrict__ a2b,
                            float4* __restrict__ amsg)
{
    int idx = blockIdx.x * blockDim.x + threadIdx.x;
    if (idx >= N_ATOMS * H4) return;
    int a = idx / H4;
    int j = idx - a * H4;
    const int* nb = a2b + (size_t)a * MAX_NB;
    float4 s = {0.f, 0.f, 0.f, 0.f};
    #pragma unroll
    for (int i = 0; i < MAX_NB; i++) {
        float4 v = msg[(size_t)nb[i] * H4 + j];
        s.x += v.x; s.y += v.y; s.z += v.z; s.w += v.w;
    }
    amsg[idx] = s;
}

__global__ void hpre4(const float4* __restrict__ amsg,
                      const float4* __restrict__ msg,
                      const int* __restrict__ b2a,
                      const int* __restrict__ b2revb,
                      float4* __restrict__ h)
{
    int idx = blockIdx.x * blockDim.x + threadIdx.x;
    if (idx >= N_BONDS * H4) return;
    int b = idx / H4;
    int j = idx - b * H4;
    float4 u = amsg[(size_t)b2a[b] * H4 + j];
    float4 v = msg[(size_t)b2revb[b] * H4 + j];
    float4 o = {u.x - v.x, u.y - v.y, u.z - v.z, u.w - v.w};
    h[idx] = o;
}

__device__ __forceinline__ float sigmoidf1(float x) { return 1.f / (1.f + expf(-x)); }

__global__ void gru4(const float4* __restrict__ gi,
                     const float4* __restrict__ gh,
                     const float4* __restrict__ h,
                     float4* __restrict__ out)
{
    int idx = blockIdx.x * blockDim.x + threadIdx.x;
    if (idx >= N_BONDS * H4) return;
    int b = idx / H4;
    int j = idx - b * H4;
    if (b == 0) { out[idx] = make_float4(0.f, 0.f, 0.f, 0.f); return; }
    size_t gb = (size_t)b * H34;
    float4 ir = gi[gb + j], iz = gi[gb + H4 + j], in4 = gi[gb + 2 * H4 + j];
    float4 hr = gh[gb + j], hz = gh[gb + H4 + j], hn4 = gh[gb + 2 * H4 + j];
    float4 hh = h[idx];
    float4 o;
    {
        float r = sigmoidf1(ir.x + hr.x), z = sigmoidf1(iz.x + hz.x);
        float n = tanhf(in4.x + r * hn4.x);
        o.x = (1.f - z) * n + z * hh.x;
    }
    {
        float r = sigmoidf1(ir.y + hr.y), z = sigmoidf1(iz.y + hz.y);
        float n = tanhf(in4.y + r * hn4.y);
        o.y = (1.f - z) * n + z * hh.y;
    }
    {
        float r = sigmoidf1(ir.z + hr.z), z = sigmoidf1(iz.z + hz.z);
        float n = tanhf(in4.z + r * hn4.z);
        o.z = (1.f - z) * n + z * hh.z;
    }
    {
        float r = sigmoidf1(ir.w + hr.w), z = sigmoidf1(iz.w + hz.w);
        float n = tanhf(in4.w + r * hn4.w);
        o.w = (1.f - z) * n + z * hh.w;
    }
    out[idx] = o;
}

__global__ void concat_kernel(const float* __restrict__ f_atoms,
                              const float* __restrict__ amsg,
                              float* __restrict__ ain)
{
    int idx = blockIdx.x * blockDim.x + threadIdx.x;
    if (idx >= N_ATOMS * CAT_DIM) return;
    int a = idx / CAT_DIM;
    int k = idx - a * CAT_DIM;
    ain[idx] = (k < ATOM_FDIM) ? f_atoms[(size_t)a * ATOM_FDIM + k]
                               : amsg[(size_t)a * HID + (k - ATOM_FDIM)];
}

// ================= launch ========================================================
static inline dim3 gemm_grid(int M, int N) {
    return dim3((N + BN - 1) / BN, (M + BM - 1) / BM);
}

extern "C" void kernel_launch(void* const* d_in, const int* in_sizes, int n_in,
                              void* d_out, int out_size)
{
    const float* f_atoms = (const float*)d_in[0];
    const float* f_bonds = (const float*)d_in[1];
    const int*   a2b     = (const int*)  d_in[2];
    const int*   b2a     = (const int*)  d_in[3];
    const int*   b2revb  = (const int*)  d_in[4];
    const float* mask    = (const float*)d_in[8];
    const float* W_i     = (const float*)d_in[9];   // [300,147]
    const float* W_ih    = (const float*)d_in[10];  // [900,300]
    const float* W_hh    = (const float*)d_in[11];  // [900,300]
    const float* b_ih    = (const float*)d_in[12];
    const float* b_hh    = (const float*)d_in[13];
    const float* W_o_w   = (const float*)d_in[14];  // [300,433]
    const float* W_o_b   = (const float*)d_in[15];
    float* out = (float*)d_out;

    float *p_inp, *p_gi, *p_msg, *p_h, *p_gh, *p_amsg, *p_ain;
    cudaGetSymbolAddress((void**)&p_inp,  g_inp);
    cudaGetSymbolAddress((void**)&p_gi,   g_gi);
    cudaGetSymbolAddress((void**)&p_msg,  g_msg);
    cudaGetSymbolAddress((void**)&p_h,    g_h);
    cudaGetSymbolAddress((void**)&p_gh,   g_gh);
    cudaGetSymbolAddress((void**)&p_amsg, g_amsg);
    cudaGetSymbolAddress((void**)&p_ain,  g_ain);

    const int EW = 256;
    int nb4_grid = (N_BONDS * H4 + EW - 1) / EW;
    int na4_grid = (N_ATOMS * H4 + EW - 1) / EW;
    int cat_grid = (N_ATOMS * CAT_DIM + EW - 1) / EW;

    // inp = f_bonds @ W_i^T            [90000,300] K=147
    mma_gemm_tn<<<gemm_grid(N_BONDS, HID), 256>>>(f_bonds, W_i, nullptr, nullptr,
                                                  p_inp, N_BONDS, HID, BOND_FDIM, 0);
    // gi = inp @ W_ih^T + b_ih         [90000,900] K=300  (loop-invariant)
    mma_gemm_tn<<<gemm_grid(N_BONDS, 3 * HID), 256>>>(p_inp, W_ih, b_ih, nullptr,
                                                      p_gi, N_BONDS, 3 * HID, HID, 0);

    const float* msg_src = p_inp;
    for (int it = 0; it < DEPTH - 1; it++) {
        gather_sum4<<<na4_grid, EW>>>((const float4*)msg_src, a2b, (float4*)p_amsg);
        hpre4<<<nb4_grid, EW>>>((const float4*)p_amsg, (const float4*)msg_src,
                                b2a, b2revb, (float4*)p_h);
        // gh = h @ W_hh^T + b_hh       [90000,900] K=300
        mma_gemm_tn<<<gemm_grid(N_BONDS, 3 * HID), 256>>>(p_h, W_hh, b_hh, nullptr,
                                                          p_gh, N_BONDS, 3 * HID, HID, 0);
        gru4<<<nb4_grid, EW>>>((const float4*)p_gi, (const float4*)p_gh,
                               (const float4*)p_h, (float4*)p_msg);
        msg_src = p_msg;
    }

    gather_sum4<<<na4_grid, EW>>>((const float4*)msg_src, a2b, (float4*)p_amsg);
    concat_kernel<<<cat_grid, EW>>>(f_atoms, p_amsg, p_ain);
    // out = relu(ain @ W_o_w^T + W_o_b) * mask   [40000,300] K=433
    mma_gemm_tn<<<gemm_grid(N_ATOMS, HID), 256>>>(p_ain, W_o_w, W_o_b, mask,
                                                  out, N_ATOMS, HID, CAT_DIM, 1);
}